// round 2
// baseline (speedup 1.0000x reference)
#include <cuda_runtime.h>
#include <cstdint>

// ---------------- problem constants ----------------
#define NIMG   8
#define BLK    32         // image block size
#define P_CNT  256        // number of blocks/regions
#define KPSF   64         // PSF size
#define SENS   1024       // sensor dim
#define KB_D   33         // binned kernel taps per axis
#define KB_W   34         // padded width (dx)
#define SB_W   97         // padded smem row width (t in [-32,64] -> 97, odd => conflict-free)

// Binned PSF: [p][phase(ry*2+rx)][dy][dx(pad 34)]
__device__ float g_Kb[P_CNT * 4 * KB_D * KB_W];

__device__ __forceinline__ unsigned long long ffma2(unsigned long long a,
                                                    unsigned long long b,
                                                    unsigned long long c) {
    unsigned long long d;
    asm("fma.rn.f32x2 %0, %1, %2, %3;" : "=l"(d) : "l"(a), "l"(b), "l"(c));
    return d;
}

// ---------------- kernel 0: zero the sensor ----------------
__global__ void zero_kernel(float4* __restrict__ out, int n4) {
    int i = blockIdx.x * blockDim.x + threadIdx.x;
    if (i < n4) out[i] = make_float4(0.f, 0.f, 0.f, 0.f);
}

// ---------------- kernel 1: bin the PSF into 4 phase kernels ----------------
// Kb[p,ry,rx,dy,dx] = sum_{a,c in {0,1}} psf[p][63-ry-2dy+a][63-rx-2dx+c] (valid idx only)
__global__ void binpsf_kernel(const float* __restrict__ psf) {
    int idx = blockIdx.x * blockDim.x + threadIdx.x;
    const int total = P_CNT * 4 * KB_D * KB_W;
    if (idx >= total) return;
    int dx = idx % KB_W;
    int dy = (idx / KB_W) % KB_D;
    int ph = (idx / (KB_W * KB_D)) & 3;
    int p  = idx / (KB_W * KB_D * 4);
    float s = 0.f;
    if (dx < KB_D) {
        int ry = ph >> 1, rx = ph & 1;
        const float* w = psf + (size_t)p * KPSF * KPSF;
        int r0 = 63 - ry - 2 * dy;
        int c0 = 63 - rx - 2 * dx;
        #pragma unroll
        for (int a = 0; a < 2; ++a) {
            int rr = r0 + a;
            if (rr < 0 || rr > 63) continue;
            #pragma unroll
            for (int c = 0; c < 2; ++c) {
                int cc = c0 + c;
                if (cc < 0 || cc > 63) continue;
                s += w[rr * KPSF + cc];
            }
        }
    }
    g_Kb[idx] = s;
}

// ---------------- kernel 2: conv (binned) + splat with atomics ----------------
// grid: 4096 CTAs = p(256) x phase(4) x npair(4). 256 threads.
// thread: 8 consecutive qx outputs x 2 packed images (f32x2), 2 qy values.
__global__ __launch_bounds__(256)
void conv_splat_kernel(const float* __restrict__ imgs,
                       const float* __restrict__ xc,
                       const float* __restrict__ yc,
                       float* __restrict__ out)
{
    const int bid = blockIdx.x;
    const int np  = bid & 3;          // image pair index
    const int ph  = (bid >> 2) & 3;   // phase
    const int p   = bid >> 4;         // region
    const int ry  = ph >> 1, rx = ph & 1;
    const int tid = threadIdx.x;

    __shared__ float2 sKb[KB_D * KB_W];   // (k,k) duplicated for 64-bit broadcast
    __shared__ float2 sB[BLK * SB_W];     // [s][tt] : (img n0, img n1), x zero-padded

    // load phase kernel, duplicated into both f32x2 lanes
    {
        const float* kb = g_Kb + ((size_t)p * 4 + ph) * KB_D * KB_W;
        for (int i = tid; i < KB_D * KB_W; i += 256) {
            float k = kb[i];
            sKb[i] = make_float2(k, k);
        }
    }
    // zero the padded block buffer (padding must be 0)
    for (int i = tid; i < BLK * SB_W; i += 256) sB[i] = make_float2(0.f, 0.f);
    __syncthreads();

    // load the two image blocks interleaved
    const int bh = p & 15, bw = p >> 4;     // p = bw*16 + bh
    {
        const float* pl0 = imgs + ((size_t)(2 * np) * 512 + bh * 32) * 512 + bw * 32;
        const float* pl1 = pl0 + (size_t)512 * 512;
        for (int i = tid; i < BLK * BLK; i += 256) {
            int s = i >> 5, t = i & 31;
            float2 v;
            v.x = pl0[s * 512 + t];
            v.y = pl1[s * 512 + t];
            sB[s * SB_W + 32 + t] = v;
        }
    }
    __syncthreads();

    // splat geometry (all in-bounds for this problem's centers)
    const int ic = 512 + __float2int_rn(xc[p] * 1e6f);
    const int jc = 512 + __float2int_rn(yc[p] * 1e6f);
    const int j0 = jc - 63 + rx;

    const int c   = tid & 7;
    const int qx0 = c << 3;           // 8 outputs along qx
    const int qyb = tid >> 3;         // 0..31

    #pragma unroll
    for (int half = 0; half < 2; ++half) {
        const int qy = qyb + 32 * half;

        unsigned long long acc[8];
        #pragma unroll
        for (int u = 0; u < 8; ++u) acc[u] = 0ULL;

        const int dlo = max(0, qy - 31);
        const int dhi = min(32, qy);
        for (int dy = dlo; dy <= dhi; ++dy) {
            const int s = qy - dy;
            const unsigned long long* row =
                reinterpret_cast<const unsigned long long*>(sB + s * SB_W);
            const unsigned long long* kr =
                reinterpret_cast<const unsigned long long*>(sKb + dy * KB_W);

            // init sliding window: t = qx0+u  (slot = t & 7 = u since qx0 % 8 == 0)
            unsigned long long win[8];
            #pragma unroll
            for (int u = 0; u < 8; ++u) win[u] = row[32 + qx0 + u];

            #pragma unroll
            for (int dx = 0; dx < 33; ++dx) {
                if (dx > 0) win[(-dx) & 7] = row[32 + qx0 - dx];  // new t = qx0-dx
                const unsigned long long k2 = kr[dx];
                #pragma unroll
                for (int u = 0; u < 8; ++u)
                    acc[u] = ffma2(k2, win[(u - dx) & 7], acc[u]);
            }
        }

        // scatter into sensor (phases are disjoint pixels; neighbors overlap -> atomics)
        const int oy = 2 * qy + ry;
        if (oy <= 126) {
            const int irow = ic - 63 + oy;
            float* o0 = out + ((size_t)(2 * np) * SENS + irow) * SENS;
            float* o1 = o0 + (size_t)SENS * SENS;
            #pragma unroll
            for (int u = 0; u < 8; ++u) {
                const int qx = qx0 + u;
                const int ox = 2 * qx + rx;
                if (ox > 126) continue;   // only rx=1, qx=63
                const int j = j0 + 2 * qx;
                float2 v = *reinterpret_cast<float2*>(&acc[u]);
                atomicAdd(o0 + j, v.x);
                atomicAdd(o1 + j, v.y);
            }
        }
    }
}

// ---------------- launch ----------------
extern "C" void kernel_launch(void* const* d_in, const int* in_sizes, int n_in,
                              void* d_out, int out_size) {
    const float* imgs = (const float*)d_in[0];
    const float* psf  = (const float*)d_in[1];
    // d_in[2], d_in[3] = X, Y meshgrids (shape only; SENS hardcoded)
    const float* xc   = (const float*)d_in[4];
    const float* yc   = (const float*)d_in[5];
    float* out = (float*)d_out;

    // zero sensor (poisoned by harness)
    {
        int n4 = out_size / 4;  // 8*1024*1024 / 4
        zero_kernel<<<(n4 + 255) / 256, 256>>>((float4*)out, n4);
    }
    // bin PSFs
    {
        int total = P_CNT * 4 * KB_D * KB_W;
        binpsf_kernel<<<(total + 255) / 256, 256>>>(psf);
    }
    // conv + splat
    conv_splat_kernel<<<P_CNT * 4 * 4, 256>>>(imgs, xc, yc, out);
}

// round 3
// speedup vs baseline: 1.7744x; 1.7744x over previous
#include <cuda_runtime.h>
#include <cstdint>

typedef unsigned long long ull;

#define SENS   1024
#define P_CNT  256
#define KPSF   64
#define T_PAD  7            // t range [-7, 38] -> 46 slots
#define T_SLOTS 46
#define SB_ULL (32 * T_SLOTS * 4)    // [s][t+7][npair] float2 as ull = 5888
#define SK_ULL (33 * 34)             // [dx][dy] dup-float2 as ull  = 1122
#define SMEM_BYTES ((SB_ULL + SK_ULL) * 8)

// Binned PSF, transposed + duplicated: [p][ph][dx(33)][dy(34 pad)] float2(k,k)
__device__ float2 g_KbT[P_CNT * 4 * 33 * 34];

__device__ __forceinline__ ull ffma2(ull a, ull b, ull c) {
    ull d;
    asm("fma.rn.f32x2 %0, %1, %2, %3;" : "=l"(d) : "l"(a), "l"(b), "l"(c));
    return d;
}

// ---------------- kernel 0: zero the sensor ----------------
__global__ void zero_kernel(float4* __restrict__ out, int n4) {
    int i = blockIdx.x * blockDim.x + threadIdx.x;
    if (i < n4) out[i] = make_float4(0.f, 0.f, 0.f, 0.f);
}

// ---------------- kernel 1: bin PSF into 4 phase kernels (transposed) ----------
// KbT[p,ph,dx,dy] = sum_{a,c in {0,1}} psf[p][63-ry-2dy+a][63-rx-2dx+c] (valid idx)
__global__ void binpsf_kernel(const float* __restrict__ psf) {
    int idx = blockIdx.x * blockDim.x + threadIdx.x;
    const int total = P_CNT * 4 * 33 * 34;
    if (idx >= total) return;
    int dy = idx % 34;
    int dx = (idx / 34) % 33;
    int ph = (idx / (34 * 33)) & 3;
    int p  = idx / (34 * 33 * 4);
    float s = 0.f;
    if (dy < 33) {
        int ry = ph >> 1, rx = ph & 1;
        const float* w = psf + (size_t)p * KPSF * KPSF;
        int r0 = 63 - ry - 2 * dy;
        int c0 = 63 - rx - 2 * dx;
        #pragma unroll
        for (int a = 0; a < 2; ++a) {
            int rr = r0 + a;
            if (rr < 0 || rr > 63) continue;
            #pragma unroll
            for (int c = 0; c < 2; ++c) {
                int cc = c0 + c;
                if (cc < 0 || cc > 63) continue;
                s += w[rr * KPSF + cc];
            }
        }
    }
    g_KbT[idx] = make_float2(s, s);
}

// ---------------- kernel 2: conv via shift-register accumulators ---------------
// grid: 1024 CTAs = p(256) x phase(4). 256 threads = 8 warps.
// warp w: qx0 = 8w (warp-uniform dx range). lane: npair = lane&3, xi = lane>>2,
// qx = qx0 + xi. Thread computes all 64 qy outputs for its (qx, image pair)
// via a 33-deep rotating accumulator bank.
__global__ __launch_bounds__(256, 2)
void conv_splat_kernel(const float* __restrict__ imgs,
                       const float* __restrict__ xc,
                       const float* __restrict__ yc,
                       float* __restrict__ out)
{
    extern __shared__ ull dynsmem[];
    ull* sB = dynsmem;              // [32][46][4]
    ull* sK = dynsmem + SB_ULL;     // [33][34]

    const int bid  = blockIdx.x;
    const int ph   = bid & 3;
    const int p    = bid >> 2;
    const int ry   = ph >> 1, rx = ph & 1;
    const int tid  = threadIdx.x;
    const int lane = tid & 31;
    const int warp = tid >> 5;
    const int npair = lane & 3;
    const int xi    = lane >> 2;
    const int qx0   = warp << 3;
    const int qx    = qx0 + xi;

    // load binned kernel (already duplicated float2)
    {
        const ull* kb8 = reinterpret_cast<const ull*>(g_KbT) + (size_t)(p * 4 + ph) * SK_ULL;
        for (int i = tid; i < SK_ULL; i += 256) sK[i] = kb8[i];
    }
    // zero padded block buffer
    for (int i = tid; i < SB_ULL; i += 256) sB[i] = 0ULL;
    __syncthreads();

    // fill interior: sB[s][t+7][np] = (img[2np][..], img[2np+1][..])
    const int bh = p & 15, bw = p >> 4;        // p = bw*16 + bh
    for (int i = tid; i < 32 * 32 * 4; i += 256) {
        int np = i & 3;
        int t  = (i >> 2) & 31;
        int s  = i >> 7;
        const float* pl = imgs + (((size_t)(2 * np) * 512 + bh * 32 + s) * 512 + bw * 32 + t);
        float2 v;
        v.x = pl[0];
        v.y = pl[512 * 512];
        sB[(s * T_SLOTS + t + T_PAD) * 4 + np] = *reinterpret_cast<ull*>(&v);
    }
    __syncthreads();

    // splat geometry (all in-bounds for this problem)
    const int ic = 512 + __float2int_rn(xc[p] * 1e6f);
    const int jc = 512 + __float2int_rn(yc[p] * 1e6f);
    const int j  = jc - 63 + rx + 2 * qx;
    const bool emitx = !(rx == 1 && qx == 63);
    float* o0 = out + (size_t)(2 * npair) * SENS * SENS + j;
    float* o1 = o0 + (size_t)SENS * SENS;
    const int irow0 = ic - 63 + ry;            // row for qy=0

    // warp-uniform dx range
    const int dxlo = max(0, qx0 - 31);
    const int dxhi = min(32, qx0 + 7);

    ull acc[33];
    #pragma unroll
    for (int i = 0; i < 33; ++i) acc[i] = 0ULL;

    #pragma unroll
    for (int s = 0; s < 32; ++s) {
        const ull* bRow = sB + (s * T_SLOTS + T_PAD + qx) * 4 + npair;
        const ull* kc   = sK + dxlo * 34;
        ull b2 = bRow[-dxlo * 4];                         // prefetch first tap
        for (int dx = dxlo; dx <= dxhi; ++dx) {
            ull bcur = b2;
            if (dx < dxhi) b2 = bRow[-(dx + 1) * 4];      // prefetch next
            #pragma unroll
            for (int e = 0; e < 16; ++e) {
                ulonglong2 kk = *reinterpret_cast<const ulonglong2*>(kc + 2 * e);
                acc[(s + 2 * e)     % 33] = ffma2(kk.x, bcur, acc[(s + 2 * e)     % 33]);
                acc[(s + 2 * e + 1) % 33] = ffma2(kk.y, bcur, acc[(s + 2 * e + 1) % 33]);
            }
            acc[(s + 32) % 33] = ffma2(kc[32], bcur, acc[(s + 32) % 33]);
            kc += 34;
        }
        // qy = s is complete: emit and recycle the slot
        if (emitx) {
            float2 v = *reinterpret_cast<float2*>(&acc[s % 33]);
            float* r0 = o0 + (size_t)(irow0 + 2 * s) * SENS;
            atomicAdd(r0, v.x);
            atomicAdd(r0 + (size_t)SENS * SENS, v.y);
        }
        acc[s % 33] = 0ULL;
    }

    // drain qy = 32..63
    #pragma unroll
    for (int qy = 32; qy < 64; ++qy) {
        const int oy = 2 * qy + ry;
        if (oy <= 126 && emitx) {
            float2 v = *reinterpret_cast<float2*>(&acc[qy % 33]);
            float* r0 = o0 + (size_t)(irow0 + 2 * qy) * SENS;
            atomicAdd(r0, v.x);
            atomicAdd(r0 + (size_t)SENS * SENS, v.y);
        }
    }
}

// ---------------- launch ----------------
extern "C" void kernel_launch(void* const* d_in, const int* in_sizes, int n_in,
                              void* d_out, int out_size) {
    const float* imgs = (const float*)d_in[0];
    const float* psf  = (const float*)d_in[1];
    const float* xc   = (const float*)d_in[4];
    const float* yc   = (const float*)d_in[5];
    float* out = (float*)d_out;

    (void)cudaFuncSetAttribute(conv_splat_kernel,
                               cudaFuncAttributeMaxDynamicSharedMemorySize, SMEM_BYTES);

    {
        int n4 = out_size / 4;
        zero_kernel<<<(n4 + 255) / 256, 256>>>((float4*)out, n4);
    }
    {
        int total = P_CNT * 4 * 33 * 34;
        binpsf_kernel<<<(total + 255) / 256, 256>>>(psf);
    }
    conv_splat_kernel<<<P_CNT * 4, 256, SMEM_BYTES>>>(imgs, xc, yc, out);
}

// round 4
// speedup vs baseline: 1.8136x; 1.0221x over previous
#include <cuda_runtime.h>
#include <cstdint>

typedef unsigned long long ull;

#define SENS   1024
#define P_CNT  256
#define KPSF   64

// smem layout: sK (1122 ull = [dx 33][dy 34pad] float2(k_rx0,k_rx1)) then
//              sBlk (32 s x 34 tslots x 9 npad floats)
#define SK_ULL   (33 * 34)
#define SB_FLT   (32 * 34 * 9)
#define SMEM_BYTES (SK_ULL * 8 + SB_FLT * 4)

// Binned PSF, phase-x paired: [p][ry][dx 33][dy 34pad] -> float2(k@rx0, k@rx1)
__device__ float2 g_K[P_CNT * 2 * 33 * 34];

__device__ __forceinline__ ull ffma2(ull a, ull b, ull c) {
    ull d;
    asm("fma.rn.f32x2 %0, %1, %2, %3;" : "=l"(d) : "l"(a), "l"(b), "l"(c));
    return d;
}
__device__ __forceinline__ ull dup2(float v) {
    ull d;
    asm("mov.b64 %0, {%1, %1};" : "=l"(d) : "f"(v));
    return d;
}

// ---------------- kernel 0: zero the sensor ----------------
__global__ void zero_kernel(float4* __restrict__ out, int n4) {
    int i = blockIdx.x * blockDim.x + threadIdx.x;
    if (i < n4) out[i] = make_float4(0.f, 0.f, 0.f, 0.f);
}

// ---------------- kernel 1: bin PSF, pair the two x-phases -------------------
// K[p,ry,rx,dx,dy] = sum_{a,c in {0,1}} psf[p][63-ry-2dy+a][63-rx-2dx+c]
__global__ void binpsf_kernel(const float* __restrict__ psf) {
    int idx = blockIdx.x * blockDim.x + threadIdx.x;
    const int total = P_CNT * 2 * 33 * 34;
    if (idx >= total) return;
    int dy = idx % 34;
    int dx = (idx / 34) % 33;
    int ry = (idx / (34 * 33)) & 1;
    int p  = idx / (34 * 33 * 2);
    float s0 = 0.f, s1 = 0.f;
    if (dy < 33) {
        const float* w = psf + (size_t)p * KPSF * KPSF;
        int r0 = 63 - ry - 2 * dy;
        #pragma unroll
        for (int rx = 0; rx < 2; ++rx) {
            int c0 = 63 - rx - 2 * dx;
            float s = 0.f;
            #pragma unroll
            for (int a = 0; a < 2; ++a) {
                int rr = r0 + a;
                if (rr < 0 || rr > 63) continue;
                #pragma unroll
                for (int c = 0; c < 2; ++c) {
                    int cc = c0 + c;
                    if (cc < 0 || cc > 63) continue;
                    s += w[rr * KPSF + cc];
                }
            }
            if (rx == 0) s0 = s; else s1 = s;
        }
    }
    g_K[idx] = make_float2(s0, s1);
}

// ---------------- kernel 2: conv, phase-x packed, shift-register acc ---------
// grid: 4096 CTAs = p(256) x ry(2) x qx-octet(8). 128 threads = 4 warps.
// warp w: qx base = octet*8 + 2w (2 consecutive qx -> dx union waste 1.03x).
// lane: n = lane&7 (image), xi = (lane>>3)&1 (qx), sh = lane>>4 (s-half).
// f32x2 lanes = (rx=0, rx=1). Thread: 48 partial outputs via 33-deep rotating
// accumulators indexed by LOCAL step (lane-invariant -> static regs).
__global__ __launch_bounds__(128, 4)
void conv_splat_kernel(const float* __restrict__ imgs,
                       const float* __restrict__ xc,
                       const float* __restrict__ yc,
                       float* __restrict__ out)
{
    extern __shared__ ull dynsmem[];
    ull*   sK   = dynsmem;                                  // [33][34] float2
    float* sBlk = reinterpret_cast<float*>(dynsmem + SK_ULL); // [32][34][9]

    const int bid  = blockIdx.x;
    const int oct  = bid & 7;
    const int ry   = (bid >> 3) & 1;
    const int p    = bid >> 4;
    const int tid  = threadIdx.x;
    const int lane = tid & 31;
    const int warp = tid >> 5;
    const int n    = lane & 7;
    const int xi   = (lane >> 3) & 1;
    const int sh   = lane >> 4;
    const int base = oct * 8 + warp * 2;
    const int qx   = base + xi;
    const int s0   = sh * 16;

    // load paired kernel
    {
        const ull* kg = reinterpret_cast<const ull*>(g_K) + (size_t)(p * 2 + ry) * SK_ULL;
        for (int i = tid; i < SK_ULL; i += 128) sK[i] = kg[i];
    }
    // zero the two pad t-columns (t = -1 and t = 32)
    for (int i = tid; i < 32 * 2 * 8; i += 128) {
        int s  = i >> 4;
        int r  = i & 15;
        int ts = (r & 1) ? 33 : 0;
        int nn = r >> 1;
        sBlk[(s * 34 + ts) * 9 + nn] = 0.f;
    }
    // fill interior (coalesced gmem reads, conflict-free STS: t coeff 9 is odd)
    const int bh = p & 15, bw = p >> 4;          // p = bw*16 + bh
    for (int i = tid; i < 32 * 32 * 8; i += 128) {
        int t  = i & 31;
        int nn = (i >> 5) & 7;
        int s  = i >> 8;
        sBlk[(s * 34 + t + 1) * 9 + nn] =
            imgs[((size_t)nn * 512 + bh * 32 + s) * 512 + bw * 32 + t];
    }
    __syncthreads();

    // splat geometry (all in-bounds for this problem's centers)
    const int ic = 512 + __float2int_rn(xc[p] * 1e6f);
    const int jc = 512 + __float2int_rn(yc[p] * 1e6f);
    const int irow0 = ic - 63 + ry;                 // sensor row for qy=0
    const int jcol  = jc - 63 + 2 * qx;             // rx=0 column; rx=1 -> +1
    float* obase = out + (size_t)n * SENS * SENS;
    const bool emity = (qx != 63);                  // rx=1, qx=63 -> ox=127 invalid

    // warp-uniform dx range (union over 2 qx)
    const int dxlo = max(0, base - 31);
    const int dxhi = min(32, base + 1);

    // per-thread b column pointer at (s = s0, t = qx - dxlo)
    const float* bcol0 = sBlk + (s0 * 34 + qx + 1) * 9 + n;

    ull acc[33];
    #pragma unroll
    for (int i = 0; i < 33; ++i) acc[i] = 0ULL;

    #pragma unroll
    for (int i = 0; i < 16; ++i) {                  // local s step; s = s0 + i
        const float* bp = bcol0 + i * (34 * 9) - dxlo * 9;
        const ull*   kc = sK + dxlo * 34;
        float bnext = *bp;
        for (int dx = dxlo; dx <= dxhi; ++dx) {
            float bv = bnext;
            bp -= 9;
            if (dx < dxhi) bnext = *bp;
            const ull bdup = dup2(bv);
            #pragma unroll
            for (int e = 0; e < 16; ++e) {
                ulonglong2 kk = *reinterpret_cast<const ulonglong2*>(kc + 2 * e);
                acc[(i + 2 * e)     % 33] = ffma2(kk.x, bdup, acc[(i + 2 * e)     % 33]);
                acc[(i + 2 * e + 1) % 33] = ffma2(kk.y, bdup, acc[(i + 2 * e + 1) % 33]);
            }
            acc[(i + 32) % 33] = ffma2(kc[32], bdup, acc[(i + 32) % 33]);
            kc += 34;
        }
        // qy = s0 + i complete within this half: emit partial, recycle slot
        {
            const int qy = s0 + i;
            float2 v = *reinterpret_cast<float2*>(&acc[i % 33]);
            float* r = obase + (size_t)(irow0 + 2 * qy) * SENS + jcol;
            atomicAdd(r, v.x);
            if (emity) atomicAdd(r + 1, v.y);
            acc[i % 33] = 0ULL;
        }
    }

    // drain slots 16..47 (qy = s0+16 .. s0+47)
    #pragma unroll
    for (int d = 16; d < 48; ++d) {
        const int qy = s0 + d;
        if (ry == 1 && qy == 63) continue;          // oy = 127 out of block
        float2 v = *reinterpret_cast<float2*>(&acc[d % 33]);
        float* r = obase + (size_t)(irow0 + 2 * qy) * SENS + jcol;
        atomicAdd(r, v.x);
        if (emity) atomicAdd(r + 1, v.y);
    }
}

// ---------------- launch ----------------
extern "C" void kernel_launch(void* const* d_in, const int* in_sizes, int n_in,
                              void* d_out, int out_size) {
    const float* imgs = (const float*)d_in[0];
    const float* psf  = (const float*)d_in[1];
    const float* xc   = (const float*)d_in[4];
    const float* yc   = (const float*)d_in[5];
    float* out = (float*)d_out;

    (void)cudaFuncSetAttribute(conv_splat_kernel,
                               cudaFuncAttributeMaxDynamicSharedMemorySize, SMEM_BYTES);

    {
        int n4 = out_size / 4;
        zero_kernel<<<(n4 + 255) / 256, 256>>>((float4*)out, n4);
    }
    {
        int total = P_CNT * 2 * 33 * 34;
        binpsf_kernel<<<(total + 255) / 256, 256>>>(psf);
    }
    conv_splat_kernel<<<P_CNT * 2 * 8, 128, SMEM_BYTES>>>(imgs, xc, yc, out);
}

// round 5
// speedup vs baseline: 2.0812x; 1.1476x over previous
#include <cuda_runtime.h>
#include <cstdint>

typedef unsigned long long ull;

#define SENS   1024
#define P_CNT  256
#define KPSF   64

// smem layout: sK (1122 ull = [dx 33][dy 34pad] float2(k_rx0,k_rx1)) then
//              sBlk (32 s x 34 tslots x 9 npad floats)
#define SK_ULL   (33 * 34)
#define SB_FLT   (32 * 34 * 9)
#define SMEM_BYTES (SK_ULL * 8 + SB_FLT * 4)

// Binned PSF, phase-x paired: [p][ry][dx 33][dy 34pad] -> float2(k@rx0, k@rx1)
__device__ float2 g_K[P_CNT * 2 * 33 * 34];

__device__ __forceinline__ ull ffma2(ull a, ull b, ull c) {
    ull d;
    asm("fma.rn.f32x2 %0, %1, %2, %3;" : "=l"(d) : "l"(a), "l"(b), "l"(c));
    return d;
}
__device__ __forceinline__ ull dup2(float v) {
    ull d;
    asm("mov.b64 %0, {%1, %1};" : "=l"(d) : "f"(v));
    return d;
}

// ---------------- kernel 0: zero the sensor ----------------
__global__ void zero_kernel(float4* __restrict__ out, int n4) {
    int i = blockIdx.x * blockDim.x + threadIdx.x;
    if (i < n4) out[i] = make_float4(0.f, 0.f, 0.f, 0.f);
}

// ---------------- kernel 1: bin PSF, pair the two x-phases -------------------
// K[p,ry,rx,dx,dy] = sum_{a,c in {0,1}} psf[p][63-ry-2dy+a][63-rx-2dx+c]
__global__ void binpsf_kernel(const float* __restrict__ psf) {
    int idx = blockIdx.x * blockDim.x + threadIdx.x;
    const int total = P_CNT * 2 * 33 * 34;
    if (idx >= total) return;
    int dy = idx % 34;
    int dx = (idx / 34) % 33;
    int ry = (idx / (34 * 33)) & 1;
    int p  = idx / (34 * 33 * 2);
    float s0 = 0.f, s1 = 0.f;
    if (dy < 33) {
        const float* w = psf + (size_t)p * KPSF * KPSF;
        int r0 = 63 - ry - 2 * dy;
        #pragma unroll
        for (int rx = 0; rx < 2; ++rx) {
            int c0 = 63 - rx - 2 * dx;
            float s = 0.f;
            #pragma unroll
            for (int a = 0; a < 2; ++a) {
                int rr = r0 + a;
                if (rr < 0 || rr > 63) continue;
                #pragma unroll
                for (int c = 0; c < 2; ++c) {
                    int cc = c0 + c;
                    if (cc < 0 || cc > 63) continue;
                    s += w[rr * KPSF + cc];
                }
            }
            if (rx == 0) s0 = s; else s1 = s;
        }
    }
    g_K[idx] = make_float2(s0, s1);
}

// ---------------- kernel 2: conv, phase-x packed, shift-register acc ---------
// grid: 4096 CTAs. Slow index = qx-octet remapped heavy-first; fast = (p, ry).
// 128 threads = 4 warps; warp w: qx base = octet*8 + 2w.
// lane: n = lane&7 (image), xi = (lane>>3)&1 (qx), sh = lane>>4 (s-half).
// f32x2 lanes = (rx=0, rx=1). 33-deep rotating accumulators, LOCAL step index.
__global__ __launch_bounds__(128, 3)
void conv_splat_kernel(const float* __restrict__ imgs,
                       const float* __restrict__ xc,
                       const float* __restrict__ yc,
                       float* __restrict__ out)
{
    extern __shared__ ull dynsmem[];
    ull*   sK   = dynsmem;                                  // [33][34] float2
    float* sBlk = reinterpret_cast<float*>(dynsmem + SK_ULL); // [32][34][9]

    const int bid  = blockIdx.x;
    // heavy-first octet ordering: groups of 512 CTAs, descending dx-trip work
    const int grp  = bid >> 9;
    const int oct  = (0x70615243u >> (grp * 4)) & 7;   // {3,4,2,5,1,6,0,7}
    const int ry   = bid & 1;
    const int p    = (bid >> 1) & 255;
    const int tid  = threadIdx.x;
    const int lane = tid & 31;
    const int warp = tid >> 5;
    const int n    = lane & 7;
    const int xi   = (lane >> 3) & 1;
    const int sh   = lane >> 4;
    const int base = oct * 8 + warp * 2;
    const int qx   = base + xi;
    const int s0   = sh * 16;

    // load paired kernel (16B vectors)
    {
        const ulonglong2* kg = reinterpret_cast<const ulonglong2*>(
            reinterpret_cast<const ull*>(g_K) + (size_t)(p * 2 + ry) * SK_ULL);
        ulonglong2* sk2 = reinterpret_cast<ulonglong2*>(sK);
        for (int i = tid; i < SK_ULL / 2; i += 128) sk2[i] = kg[i];
    }
    // zero the two pad t-columns (t = -1 and t = 32)
    for (int i = tid; i < 32 * 2 * 8; i += 128) {
        int s  = i >> 4;
        int r  = i & 15;
        int ts = (r & 1) ? 33 : 0;
        int nn = r >> 1;
        sBlk[(s * 34 + ts) * 9 + nn] = 0.f;
    }
    // fill interior with float4 gmem loads (stride-9 scalar STS, conflict-free)
    const int bh = p & 15, bw = p >> 4;          // p = bw*16 + bh
    for (int i = tid; i < 32 * 8 * 8; i += 128) {
        int q  = i & 7;                           // float4 quad within row
        int nn = (i >> 3) & 7;
        int s  = i >> 6;
        float4 v = *reinterpret_cast<const float4*>(
            imgs + ((size_t)nn * 512 + bh * 32 + s) * 512 + bw * 32 + 4 * q);
        float* dst = &sBlk[(s * 34 + 4 * q + 1) * 9 + nn];
        dst[0]      = v.x;
        dst[9]      = v.y;
        dst[18]     = v.z;
        dst[27]     = v.w;
    }
    __syncthreads();

    // splat geometry (all in-bounds for this problem's centers)
    const int ic = 512 + __float2int_rn(xc[p] * 1e6f);
    const int jc = 512 + __float2int_rn(yc[p] * 1e6f);
    const int irow0 = ic - 63 + ry;                 // sensor row for qy=0
    const int jcol  = jc - 63 + 2 * qx;             // rx=0 column; rx=1 -> +1
    float* obase = out + (size_t)n * SENS * SENS;
    const bool emity = (qx != 63);                  // rx=1, qx=63 -> ox=127 invalid

    // warp-uniform dx range (union over 2 qx)
    const int dxlo = max(0, base - 31);
    const int dxhi = min(32, base + 1);

    // per-thread b column pointer at (s = s0, t = qx - dxlo)
    const float* bcol0 = sBlk + (s0 * 34 + qx + 1) * 9 + n;

    ull acc[33];
    #pragma unroll
    for (int i = 0; i < 33; ++i) acc[i] = 0ULL;

    #pragma unroll
    for (int i = 0; i < 16; ++i) {                  // local s step; s = s0 + i
        const float* bp = bcol0 + i * (34 * 9) - dxlo * 9;
        const ull*   kc = sK + dxlo * 34;
        float bnext = *bp;
        for (int dx = dxlo; dx <= dxhi; ++dx) {
            float bv = bnext;
            bp -= 9;
            if (dx < dxhi) bnext = *bp;
            const ull bdup = dup2(bv);
            #pragma unroll
            for (int e = 0; e < 16; ++e) {
                ulonglong2 kk = *reinterpret_cast<const ulonglong2*>(kc + 2 * e);
                acc[(i + 2 * e)     % 33] = ffma2(kk.x, bdup, acc[(i + 2 * e)     % 33]);
                acc[(i + 2 * e + 1) % 33] = ffma2(kk.y, bdup, acc[(i + 2 * e + 1) % 33]);
            }
            acc[(i + 32) % 33] = ffma2(kc[32], bdup, acc[(i + 32) % 33]);
            kc += 34;
        }
        // qy = s0 + i complete within this half: emit partial, recycle slot
        {
            const int qy = s0 + i;
            float2 v = *reinterpret_cast<float2*>(&acc[i % 33]);
            float* r = obase + (size_t)(irow0 + 2 * qy) * SENS + jcol;
            atomicAdd(r, v.x);
            if (emity) atomicAdd(r + 1, v.y);
            acc[i % 33] = 0ULL;
        }
    }

    // drain slots 16..47 (qy = s0+16 .. s0+47)
    #pragma unroll
    for (int d = 16; d < 48; ++d) {
        const int qy = s0 + d;
        if (ry == 1 && qy == 63) continue;          // oy = 127 out of block
        float2 v = *reinterpret_cast<float2*>(&acc[d % 33]);
        float* r = obase + (size_t)(irow0 + 2 * qy) * SENS + jcol;
        atomicAdd(r, v.x);
        if (emity) atomicAdd(r + 1, v.y);
    }
}

// ---------------- launch ----------------
extern "C" void kernel_launch(void* const* d_in, const int* in_sizes, int n_in,
                              void* d_out, int out_size) {
    const float* imgs = (const float*)d_in[0];
    const float* psf  = (const float*)d_in[1];
    const float* xc   = (const float*)d_in[4];
    const float* yc   = (const float*)d_in[5];
    float* out = (float*)d_out;

    (void)cudaFuncSetAttribute(conv_splat_kernel,
                               cudaFuncAttributeMaxDynamicSharedMemorySize, SMEM_BYTES);

    {
        int n4 = out_size / 4;
        zero_kernel<<<(n4 + 255) / 256, 256>>>((float4*)out, n4);
    }
    {
        int total = P_CNT * 2 * 33 * 34;
        binpsf_kernel<<<(total + 255) / 256, 256>>>(psf);
    }
    conv_splat_kernel<<<P_CNT * 2 * 8, 128, SMEM_BYTES>>>(imgs, xc, yc, out);
}

// round 6
// speedup vs baseline: 3.3362x; 1.6030x over previous
#include <cuda_runtime.h>
#include <cstdint>

typedef unsigned long long ull;

#define SENS   1024
#define P_CNT  256
#define KPSF   64

// smem layout: sK (1122 ull = [dx 33][dy 34pad] float2(k_rx0,k_rx1)) then
//              sBlk (32 s x 34 tslots x 9 npad floats)
#define SK_ULL   (33 * 34)
#define SB_FLT   (32 * 34 * 9)
#define SMEM_BYTES (SK_ULL * 8 + SB_FLT * 4)

// Binned PSF, phase-x paired: [p][ry][dx 33][dy 34pad] -> float2(k@rx0, k@rx1)
__device__ float2 g_K[P_CNT * 2 * 33 * 34];

__device__ __forceinline__ ull ffma2(ull a, ull b, ull c) {
    ull d;
    asm("fma.rn.f32x2 %0, %1, %2, %3;" : "=l"(d) : "l"(a), "l"(b), "l"(c));
    return d;
}
__device__ __forceinline__ ull dup2(float v) {
    ull d;
    asm("mov.b64 %0, {%1, %1};" : "=l"(d) : "f"(v));
    return d;
}

// ---------------- kernel 0: zero the sensor ----------------
__global__ void zero_kernel(float4* __restrict__ out, int n4) {
    int i = blockIdx.x * blockDim.x + threadIdx.x;
    if (i < n4) out[i] = make_float4(0.f, 0.f, 0.f, 0.f);
}

// ---------------- kernel 1: bin PSF, pair the two x-phases -------------------
// K[p,ry,rx,dx,dy] = sum_{a,c in {0,1}} psf[p][63-ry-2dy+a][63-rx-2dx+c]
__global__ void binpsf_kernel(const float* __restrict__ psf) {
    int idx = blockIdx.x * blockDim.x + threadIdx.x;
    const int total = P_CNT * 2 * 33 * 34;
    if (idx >= total) return;
    int dy = idx % 34;
    int dx = (idx / 34) % 33;
    int ry = (idx / (34 * 33)) & 1;
    int p  = idx / (34 * 33 * 2);
    float s0 = 0.f, s1 = 0.f;
    if (dy < 33) {
        const float* w = psf + (size_t)p * KPSF * KPSF;
        int r0 = 63 - ry - 2 * dy;
        #pragma unroll
        for (int rx = 0; rx < 2; ++rx) {
            int c0 = 63 - rx - 2 * dx;
            float s = 0.f;
            #pragma unroll
            for (int a = 0; a < 2; ++a) {
                int rr = r0 + a;
                if (rr < 0 || rr > 63) continue;
                #pragma unroll
                for (int c = 0; c < 2; ++c) {
                    int cc = c0 + c;
                    if (cc < 0 || cc > 63) continue;
                    s += w[rr * KPSF + cc];
                }
            }
            if (rx == 0) s0 = s; else s1 = s;
        }
    }
    g_K[idx] = make_float2(s0, s1);
}

// ---------------- kernel 2: conv, 4 s-steps jointly per dx pass --------------
// grid: 4096 CTAs. Slow index = qx-octet remapped heavy-first; fast = (p, ry).
// 128 threads = 4 warps; warp w: qx base = octet*8 + 2w.
// lane: n = lane&7 (image), xi = (lane>>3)&1 (qx), sh = lane>>4 (s-half).
// f32x2 lanes = (rx=0, rx=1). 36-deep rotating accumulators; each kk column
// load amortized over 4 input rows (17 LDS.128 + 4 LDS.32 per 132 FFMA2).
__global__ __launch_bounds__(128, 3)
void conv_splat_kernel(const float* __restrict__ imgs,
                       const float* __restrict__ xc,
                       const float* __restrict__ yc,
                       float* __restrict__ out)
{
    extern __shared__ ull dynsmem[];
    ull*   sK   = dynsmem;                                  // [33][34] float2
    float* sBlk = reinterpret_cast<float*>(dynsmem + SK_ULL); // [32][34][9]

    const int bid  = blockIdx.x;
    // heavy-first octet ordering: groups of 512 CTAs, descending dx-trip work
    const int grp  = bid >> 9;
    const int oct  = (0x70615243u >> (grp * 4)) & 7;   // {3,4,2,5,1,6,0,7}
    const int ry   = bid & 1;
    const int p    = (bid >> 1) & 255;
    const int tid  = threadIdx.x;
    const int lane = tid & 31;
    const int warp = tid >> 5;
    const int n    = lane & 7;
    const int xi   = (lane >> 3) & 1;
    const int sh   = lane >> 4;
    const int base = oct * 8 + warp * 2;
    const int qx   = base + xi;
    const int s0   = sh * 16;

    // load paired kernel (16B vectors)
    {
        const ulonglong2* kg = reinterpret_cast<const ulonglong2*>(
            reinterpret_cast<const ull*>(g_K) + (size_t)(p * 2 + ry) * SK_ULL);
        ulonglong2* sk2 = reinterpret_cast<ulonglong2*>(sK);
        for (int i = tid; i < SK_ULL / 2; i += 128) sk2[i] = kg[i];
    }
    // zero the two pad t-columns (t = -1 and t = 32)
    for (int i = tid; i < 32 * 2 * 8; i += 128) {
        int s  = i >> 4;
        int r  = i & 15;
        int ts = (r & 1) ? 33 : 0;
        int nn = r >> 1;
        sBlk[(s * 34 + ts) * 9 + nn] = 0.f;
    }
    // fill interior with float4 gmem loads (stride-9 scalar STS, conflict-free)
    const int bh = p & 15, bw = p >> 4;          // p = bw*16 + bh
    for (int i = tid; i < 32 * 8 * 8; i += 128) {
        int q  = i & 7;                           // float4 quad within row
        int nn = (i >> 3) & 7;
        int s  = i >> 6;
        float4 v = *reinterpret_cast<const float4*>(
            imgs + ((size_t)nn * 512 + bh * 32 + s) * 512 + bw * 32 + 4 * q);
        float* dst = &sBlk[(s * 34 + 4 * q + 1) * 9 + nn];
        dst[0]      = v.x;
        dst[9]      = v.y;
        dst[18]     = v.z;
        dst[27]     = v.w;
    }
    __syncthreads();

    // splat geometry (all in-bounds for this problem's centers)
    const int ic = 512 + __float2int_rn(xc[p] * 1e6f);
    const int jc = 512 + __float2int_rn(yc[p] * 1e6f);
    const int irow0 = ic - 63 + ry;                 // sensor row for qy=0
    const int jcol  = jc - 63 + 2 * qx;             // rx=0 column; rx=1 -> +1
    float* obase = out + (size_t)n * SENS * SENS;
    const bool emity = (qx != 63);                  // rx=1, qx=63 -> ox=127 invalid

    // warp-uniform dx range (union over 2 qx)
    const int dxlo = max(0, base - 31);
    const int dxhi = min(32, base + 1);

    // per-thread b column pointer at (s = s0, t = qx - dxlo)
    const float* bcol0 = sBlk + (s0 * 34 + qx + 1) * 9 + n;

    ull acc[36];
    #pragma unroll
    for (int i = 0; i < 36; ++i) acc[i] = 0ULL;

    #pragma unroll
    for (int i = 0; i < 16; i += 4) {               // 4 local s-steps jointly
        const float* bp = bcol0 + i * (34 * 9) - dxlo * 9;
        const ull*   kc = sK + dxlo * 34;
        for (int dx = dxlo; dx <= dxhi; ++dx) {
            ull bd[4];
            #pragma unroll
            for (int j = 0; j < 4; ++j) bd[j] = dup2(bp[j * (34 * 9)]);
            bp -= 9;
            #pragma unroll
            for (int e = 0; e < 16; ++e) {
                ulonglong2 kk = *reinterpret_cast<const ulonglong2*>(kc + 2 * e);
                #pragma unroll
                for (int j = 0; j < 4; ++j) {
                    acc[(i + j + 2 * e)     % 36] = ffma2(kk.x, bd[j], acc[(i + j + 2 * e)     % 36]);
                    acc[(i + j + 2 * e + 1) % 36] = ffma2(kk.y, bd[j], acc[(i + j + 2 * e + 1) % 36]);
                }
            }
            const ull k32 = kc[32];
            #pragma unroll
            for (int j = 0; j < 4; ++j)
                acc[(i + j + 32) % 36] = ffma2(k32, bd[j], acc[(i + j + 32) % 36]);
            kc += 34;
        }
        // qy = s0+i .. s0+i+3 complete within this half: emit, recycle slots
        #pragma unroll
        for (int j = 0; j < 4; ++j) {
            const int qy = s0 + i + j;
            float2 v = *reinterpret_cast<float2*>(&acc[(i + j) % 36]);
            float* r = obase + (size_t)(irow0 + 2 * qy) * SENS + jcol;
            atomicAdd(r, v.x);
            if (emity) atomicAdd(r + 1, v.y);
            acc[(i + j) % 36] = 0ULL;
        }
    }

    // drain slots for local qy = 16..47
    #pragma unroll
    for (int d = 16; d < 48; ++d) {
        const int qy = s0 + d;
        if (ry == 1 && qy == 63) continue;          // oy = 127 out of block
        float2 v = *reinterpret_cast<float2*>(&acc[d % 36]);
        float* r = obase + (size_t)(irow0 + 2 * qy) * SENS + jcol;
        atomicAdd(r, v.x);
        if (emity) atomicAdd(r + 1, v.y);
    }
}

// ---------------- launch ----------------
extern "C" void kernel_launch(void* const* d_in, const int* in_sizes, int n_in,
                              void* d_out, int out_size) {
    const float* imgs = (const float*)d_in[0];
    const float* psf  = (const float*)d_in[1];
    const float* xc   = (const float*)d_in[4];
    const float* yc   = (const float*)d_in[5];
    float* out = (float*)d_out;

    (void)cudaFuncSetAttribute(conv_splat_kernel,
                               cudaFuncAttributeMaxDynamicSharedMemorySize, SMEM_BYTES);

    {
        int n4 = out_size / 4;
        zero_kernel<<<(n4 + 255) / 256, 256>>>((float4*)out, n4);
    }
    {
        int total = P_CNT * 2 * 33 * 34;
        binpsf_kernel<<<(total + 255) / 256, 256>>>(psf);
    }
    conv_splat_kernel<<<P_CNT * 2 * 8, 128, SMEM_BYTES>>>(imgs, xc, yc, out);
}

// round 7
// speedup vs baseline: 3.5948x; 1.0775x over previous
#include <cuda_runtime.h>
#include <cstdint>

typedef unsigned long long ull;

#define SENS   1024
#define P_CNT  256
#define KPSF   64

#define SROW   305                    // sBlk row stride (odd => conflict-free)
#define SK_ULL   (33 * 34)            // [dx 33][dy 34pad] float2(k_rx0,k_rx1)
#define SB_FLT   (32 * SROW + 4)      // [s][ts 34 * 9 + n], ts=0/33 are zero pads
#define SMEM_BYTES (SK_ULL * 8 + SB_FLT * 4)

// Binned PSF, phase-x paired: [p][ry][dx 33][dy 34pad] -> float2(k@rx0, k@rx1)
__device__ float2 g_K[P_CNT * 2 * 33 * 34];

__device__ __forceinline__ ull ffma2(ull a, ull b, ull c) {
    ull d;
    asm("fma.rn.f32x2 %0, %1, %2, %3;" : "=l"(d) : "l"(a), "l"(b), "l"(c));
    return d;
}
__device__ __forceinline__ ull dup2(float v) {
    ull d;
    asm("mov.b64 %0, {%1, %1};" : "=l"(d) : "f"(v));
    return d;
}

// ---------------- kernel 0: zero the sensor ----------------
__global__ void zero_kernel(float4* __restrict__ out, int n4) {
    int i = blockIdx.x * blockDim.x + threadIdx.x;
    if (i < n4) out[i] = make_float4(0.f, 0.f, 0.f, 0.f);
}

// ---------------- kernel 1: bin PSF, pair the two x-phases -------------------
// K[p,ry,rx,dx,dy] = sum_{a,c in {0,1}} psf[p][63-ry-2dy+a][63-rx-2dx+c]
__global__ void binpsf_kernel(const float* __restrict__ psf) {
    int idx = blockIdx.x * blockDim.x + threadIdx.x;
    const int total = P_CNT * 2 * 33 * 34;
    if (idx >= total) return;
    int dy = idx % 34;
    int dx = (idx / 34) % 33;
    int ry = (idx / (34 * 33)) & 1;
    int p  = idx / (34 * 33 * 2);
    float s0 = 0.f, s1 = 0.f;
    if (dy < 33) {
        const float* w = psf + (size_t)p * KPSF * KPSF;
        int r0 = 63 - ry - 2 * dy;
        #pragma unroll
        for (int rx = 0; rx < 2; ++rx) {
            int c0 = 63 - rx - 2 * dx;
            float s = 0.f;
            #pragma unroll
            for (int a = 0; a < 2; ++a) {
                int rr = r0 + a;
                if (rr < 0 || rr > 63) continue;
                #pragma unroll
                for (int c = 0; c < 2; ++c) {
                    int cc = c0 + c;
                    if (cc < 0 || cc > 63) continue;
                    s += w[rr * KPSF + cc];
                }
            }
            if (rx == 0) s0 = s; else s1 = s;
        }
    }
    g_K[idx] = make_float2(s0, s1);
}

// ---------------- kernel 2: conv, 8 s-steps jointly per dx pass --------------
// grid: 4096 CTAs. Slow index = qx-octet remapped heavy-first; fast = (p, ry).
// 128 threads = 4 warps; warp w: qx base = octet*8 + 2w.
// lane: n = lane&7 (image), xi = (lane>>3)&1 (qx), sh = lane>>4 (s-half).
// f32x2 lanes = (rx=0, rx=1). 40-deep rotating accumulators; each kk column
// load amortized over 8 input rows (17 LDS.128 + 8 LDS.32 per 264 FFMA2),
// with cross-dx b prefetch to hide LDS latency.
__global__ __launch_bounds__(128, 3)
void conv_splat_kernel(const float* __restrict__ imgs,
                       const float* __restrict__ xc,
                       const float* __restrict__ yc,
                       float* __restrict__ out)
{
    extern __shared__ ull dynsmem[];
    ull*   sK   = dynsmem;                                  // [33][34] float2
    float* sBlk = reinterpret_cast<float*>(dynsmem + SK_ULL); // [s][ts*9+n], stride 305

    const int bid  = blockIdx.x;
    // heavy-first octet ordering: groups of 512 CTAs, descending dx-trip work
    const int grp  = bid >> 9;
    const int oct  = (0x70615243u >> (grp * 4)) & 7;   // {3,4,2,5,1,6,0,7}
    const int ry   = bid & 1;
    const int p    = (bid >> 1) & 255;
    const int tid  = threadIdx.x;
    const int lane = tid & 31;
    const int warp = tid >> 5;
    const int n    = lane & 7;
    const int xi   = (lane >> 3) & 1;
    const int sh   = lane >> 4;
    const int base = oct * 8 + warp * 2;
    const int qx   = base + xi;
    const int s0   = sh * 16;

    // load paired kernel (16B vectors)
    {
        const ulonglong2* kg = reinterpret_cast<const ulonglong2*>(
            reinterpret_cast<const ull*>(g_K) + (size_t)(p * 2 + ry) * SK_ULL);
        ulonglong2* sk2 = reinterpret_cast<ulonglong2*>(sK);
        for (int i = tid; i < SK_ULL / 2; i += 128) sk2[i] = kg[i];
    }
    // zero the two pad t-columns (ts = 0 and ts = 33)
    for (int i = tid; i < 32 * 2 * 8; i += 128) {
        int s  = i >> 4;
        int r  = i & 15;
        int ts = (r & 1) ? 33 : 0;
        int nn = r >> 1;
        sBlk[s * SROW + ts * 9 + nn] = 0.f;
    }
    // fill interior with float4 gmem loads (stride-9 scalar STS, conflict-free)
    const int bh = p & 15, bw = p >> 4;          // p = bw*16 + bh
    for (int i = tid; i < 32 * 8 * 8; i += 128) {
        int q  = i & 7;                           // float4 quad within row
        int nn = (i >> 3) & 7;
        int s  = i >> 6;
        float4 v = *reinterpret_cast<const float4*>(
            imgs + ((size_t)nn * 512 + bh * 32 + s) * 512 + bw * 32 + 4 * q);
        float* dst = &sBlk[s * SROW + (4 * q + 1) * 9 + nn];
        dst[0]      = v.x;
        dst[9]      = v.y;
        dst[18]     = v.z;
        dst[27]     = v.w;
    }
    __syncthreads();

    // splat geometry (all in-bounds for this problem's centers)
    const int ic = 512 + __float2int_rn(xc[p] * 1e6f);
    const int jc = 512 + __float2int_rn(yc[p] * 1e6f);
    const int irow0 = ic - 63 + ry;                 // sensor row for qy=0
    const int jcol  = jc - 63 + 2 * qx;             // rx=0 column; rx=1 -> +1
    float* obase = out + (size_t)n * SENS * SENS;
    const bool emity = (qx != 63);                  // rx=1, qx=63 -> ox=127 invalid

    // warp-uniform dx range (union over 2 qx)
    const int dxlo = max(0, base - 31);
    const int dxhi = min(32, base + 1);

    // per-thread b column base at (s = s0, ts = qx+1)
    const float* bcol0 = sBlk + s0 * SROW + (qx + 1) * 9 + n;

    ull acc[40];
    #pragma unroll
    for (int i = 0; i < 40; ++i) acc[i] = 0ULL;

    #pragma unroll
    for (int i = 0; i < 16; i += 8) {               // 8 local s-steps jointly
        const float* bp = bcol0 + i * SROW - dxlo * 9;
        const ull*   kc = sK + dxlo * 34;
        float braw[8];
        #pragma unroll
        for (int j = 0; j < 8; ++j) braw[j] = bp[j * SROW];
        for (int dx = dxlo; dx <= dxhi; ++dx) {
            ull bd[8];
            #pragma unroll
            for (int j = 0; j < 8; ++j) bd[j] = dup2(braw[j]);
            bp -= 9;
            if (dx < dxhi) {
                #pragma unroll
                for (int j = 0; j < 8; ++j) braw[j] = bp[j * SROW];
            }
            #pragma unroll
            for (int e = 0; e < 16; ++e) {
                ulonglong2 kk = *reinterpret_cast<const ulonglong2*>(kc + 2 * e);
                #pragma unroll
                for (int j = 0; j < 8; ++j) {
                    acc[(i + j + 2 * e)     % 40] = ffma2(kk.x, bd[j], acc[(i + j + 2 * e)     % 40]);
                    acc[(i + j + 2 * e + 1) % 40] = ffma2(kk.y, bd[j], acc[(i + j + 2 * e + 1) % 40]);
                }
            }
            const ull k32 = kc[32];
            #pragma unroll
            for (int j = 0; j < 8; ++j)
                acc[(i + j + 32) % 40] = ffma2(k32, bd[j], acc[(i + j + 32) % 40]);
            kc += 34;
        }
        // qy = s0+i .. s0+i+7 complete within this half: emit, recycle slots
        #pragma unroll
        for (int j = 0; j < 8; ++j) {
            const int qy = s0 + i + j;
            float2 v = *reinterpret_cast<float2*>(&acc[(i + j) % 40]);
            float* r = obase + (size_t)(irow0 + 2 * qy) * SENS + jcol;
            atomicAdd(r, v.x);
            if (emity) atomicAdd(r + 1, v.y);
            acc[(i + j) % 40] = 0ULL;
        }
    }

    // drain slots for local qy = 16..47
    #pragma unroll
    for (int d = 16; d < 48; ++d) {
        const int qy = s0 + d;
        if (ry == 1 && qy == 63) continue;          // oy = 127 out of block
        float2 v = *reinterpret_cast<float2*>(&acc[d % 40]);
        float* r = obase + (size_t)(irow0 + 2 * qy) * SENS + jcol;
        atomicAdd(r, v.x);
        if (emity) atomicAdd(r + 1, v.y);
    }
}

// ---------------- launch ----------------
extern "C" void kernel_launch(void* const* d_in, const int* in_sizes, int n_in,
                              void* d_out, int out_size) {
    const float* imgs = (const float*)d_in[0];
    const float* psf  = (const float*)d_in[1];
    const float* xc   = (const float*)d_in[4];
    const float* yc   = (const float*)d_in[5];
    float* out = (float*)d_out;

    (void)cudaFuncSetAttribute(conv_splat_kernel,
                               cudaFuncAttributeMaxDynamicSharedMemorySize, SMEM_BYTES);

    {
        int n4 = out_size / 4;
        zero_kernel<<<(n4 + 255) / 256, 256>>>((float4*)out, n4);
    }
    {
        int total = P_CNT * 2 * 33 * 34;
        binpsf_kernel<<<(total + 255) / 256, 256>>>(psf);
    }
    conv_splat_kernel<<<P_CNT * 2 * 8, 128, SMEM_BYTES>>>(imgs, xc, yc, out);
}

// round 8
// speedup vs baseline: 3.5979x; 1.0009x over previous
#include <cuda_runtime.h>
#include <cstdint>

typedef unsigned long long ull;

#define SENS   1024
#define P_CNT  256
#define KPSF   64

#define SROW   305                    // sBlk row stride (odd => conflict-free)
#define SK_ULL   (33 * 34)            // [dx 33][dy 34pad] float2(k_rx0,k_rx1)
#define SB_FLT   (32 * SROW + 4)      // [s][ts 34 * 9 + n], ts=0/33 are zero pads
#define SMEM_BYTES (SK_ULL * 8 + SB_FLT * 4)

#define ZERO_CTAS   8192              // 8*1024*1024 floats / 4 / 256
#define BINPSF_TOT  (P_CNT * 2 * 33 * 34)
#define BINPSF_CTAS ((BINPSF_TOT + 255) / 256)

// Binned PSF, phase-x paired: [p][ry][dx 33][dy 34pad] -> float2(k@rx0, k@rx1)
__device__ float2 g_K[P_CNT * 2 * 33 * 34];

__device__ __forceinline__ ull ffma2(ull a, ull b, ull c) {
    ull d;
    asm("fma.rn.f32x2 %0, %1, %2, %3;" : "=l"(d) : "l"(a), "l"(b), "l"(c));
    return d;
}
__device__ __forceinline__ ull dup2(float v) {
    ull d;
    asm("mov.b64 %0, {%1, %1};" : "=l"(d) : "f"(v));
    return d;
}

// ---------------- kernel 1: setup = zero sensor + bin PSF (merged) -----------
// CTAs [0, ZERO_CTAS): zero the sensor. CTAs [ZERO_CTAS, ...): bin the PSF.
// K[p,ry,rx,dx,dy] = sum_{a,c in {0,1}} psf[p][63-ry-2dy+a][63-rx-2dx+c]
__global__ void setup_kernel(const float* __restrict__ psf,
                             float4* __restrict__ out) {
    const int bid = blockIdx.x;
    if (bid < ZERO_CTAS) {
        out[bid * 256 + threadIdx.x] = make_float4(0.f, 0.f, 0.f, 0.f);
        return;
    }
    int idx = (bid - ZERO_CTAS) * 256 + threadIdx.x;
    if (idx >= BINPSF_TOT) return;
    int dy = idx % 34;
    int dx = (idx / 34) % 33;
    int ry = (idx / (34 * 33)) & 1;
    int p  = idx / (34 * 33 * 2);
    float s0 = 0.f, s1 = 0.f;
    if (dy < 33) {
        const float* w = psf + (size_t)p * KPSF * KPSF;
        int r0 = 63 - ry - 2 * dy;
        #pragma unroll
        for (int rx = 0; rx < 2; ++rx) {
            int c0 = 63 - rx - 2 * dx;
            float s = 0.f;
            #pragma unroll
            for (int a = 0; a < 2; ++a) {
                int rr = r0 + a;
                if (rr < 0 || rr > 63) continue;
                #pragma unroll
                for (int c = 0; c < 2; ++c) {
                    int cc = c0 + c;
                    if (cc < 0 || cc > 63) continue;
                    s += w[rr * KPSF + cc];
                }
            }
            if (rx == 0) s0 = s; else s1 = s;
        }
    }
    g_K[idx] = make_float2(s0, s1);
}

// ---------------- kernel 2: conv, 8 s-steps jointly, kk double-buffered ------
// grid: 4096 CTAs. Slow index = qx-octet remapped heavy-first; fast = (p, ry).
// 128 threads = 4 warps; warp w: qx base = octet*8 + 2w.
// lane: n = lane&7 (image), xi = (lane>>3)&1 (qx), sh = lane>>4 (s-half).
// f32x2 lanes = (rx=0, rx=1). 40-deep rotating accumulators; kk column loads
// amortized over 8 rows AND 2-stage pipelined (load e+1 during FMA of e).
__global__ __launch_bounds__(128, 3)
void conv_splat_kernel(const float* __restrict__ imgs,
                       const float* __restrict__ xc,
                       const float* __restrict__ yc,
                       float* __restrict__ out)
{
    extern __shared__ ull dynsmem[];
    ull*   sK   = dynsmem;                                  // [33][34] float2
    float* sBlk = reinterpret_cast<float*>(dynsmem + SK_ULL); // [s][ts*9+n], stride 305

    const int bid  = blockIdx.x;
    // heavy-first octet ordering: groups of 512 CTAs, descending dx-trip work
    const int grp  = bid >> 9;
    const int oct  = (0x70615243u >> (grp * 4)) & 7;   // {3,4,2,5,1,6,0,7}
    const int ry   = bid & 1;
    const int p    = (bid >> 1) & 255;
    const int tid  = threadIdx.x;
    const int lane = tid & 31;
    const int warp = tid >> 5;
    const int n    = lane & 7;
    const int xi   = (lane >> 3) & 1;
    const int sh   = lane >> 4;
    const int base = oct * 8 + warp * 2;
    const int qx   = base + xi;
    const int s0   = sh * 16;

    // load paired kernel (16B vectors)
    {
        const ulonglong2* kg = reinterpret_cast<const ulonglong2*>(
            reinterpret_cast<const ull*>(g_K) + (size_t)(p * 2 + ry) * SK_ULL);
        ulonglong2* sk2 = reinterpret_cast<ulonglong2*>(sK);
        for (int i = tid; i < SK_ULL / 2; i += 128) sk2[i] = kg[i];
    }
    // zero the two pad t-columns (ts = 0 and ts = 33)
    for (int i = tid; i < 32 * 2 * 8; i += 128) {
        int s  = i >> 4;
        int r  = i & 15;
        int ts = (r & 1) ? 33 : 0;
        int nn = r >> 1;
        sBlk[s * SROW + ts * 9 + nn] = 0.f;
    }
    // fill interior with float4 gmem loads (stride-9 scalar STS, conflict-free)
    const int bh = p & 15, bw = p >> 4;          // p = bw*16 + bh
    for (int i = tid; i < 32 * 8 * 8; i += 128) {
        int q  = i & 7;                           // float4 quad within row
        int nn = (i >> 3) & 7;
        int s  = i >> 6;
        float4 v = *reinterpret_cast<const float4*>(
            imgs + ((size_t)nn * 512 + bh * 32 + s) * 512 + bw * 32 + 4 * q);
        float* dst = &sBlk[s * SROW + (4 * q + 1) * 9 + nn];
        dst[0]      = v.x;
        dst[9]      = v.y;
        dst[18]     = v.z;
        dst[27]     = v.w;
    }
    __syncthreads();

    // splat geometry (all in-bounds for this problem's centers)
    const int ic = 512 + __float2int_rn(xc[p] * 1e6f);
    const int jc = 512 + __float2int_rn(yc[p] * 1e6f);
    const int irow0 = ic - 63 + ry;                 // sensor row for qy=0
    const int jcol  = jc - 63 + 2 * qx;             // rx=0 column; rx=1 -> +1
    float* obase = out + (size_t)n * SENS * SENS;
    const bool emity = (qx != 63);                  // rx=1, qx=63 -> ox=127 invalid

    // warp-uniform dx range (union over 2 qx)
    const int dxlo = max(0, base - 31);
    const int dxhi = min(32, base + 1);

    // per-thread b column base at (s = s0, ts = qx+1)
    const float* bcol0 = sBlk + s0 * SROW + (qx + 1) * 9 + n;

    ull acc[40];
    #pragma unroll
    for (int i = 0; i < 40; ++i) acc[i] = 0ULL;

    #pragma unroll
    for (int i = 0; i < 16; i += 8) {               // 8 local s-steps jointly
        const float* bp = bcol0 + i * SROW - dxlo * 9;
        const ull*   kc = sK + dxlo * 34;
        float braw[8];
        #pragma unroll
        for (int j = 0; j < 8; ++j) braw[j] = bp[j * SROW];
        for (int dx = dxlo; dx <= dxhi; ++dx) {
            ull bd[8];
            #pragma unroll
            for (int j = 0; j < 8; ++j) bd[j] = dup2(braw[j]);
            bp -= 9;
            if (dx < dxhi) {
                #pragma unroll
                for (int j = 0; j < 8; ++j) braw[j] = bp[j * SROW];
            }
            // 2-stage pipelined kk stream: load pair e+1 while FMA-ing pair e
            ulonglong2 kk0 = *reinterpret_cast<const ulonglong2*>(kc);
            #pragma unroll
            for (int e = 0; e < 16; ++e) {
                ulonglong2 kk1;
                if (e < 15)
                    kk1 = *reinterpret_cast<const ulonglong2*>(kc + 2 * (e + 1));
                #pragma unroll
                for (int j = 0; j < 8; ++j) {
                    acc[(i + j + 2 * e)     % 40] = ffma2(kk0.x, bd[j], acc[(i + j + 2 * e)     % 40]);
                    acc[(i + j + 2 * e + 1) % 40] = ffma2(kk0.y, bd[j], acc[(i + j + 2 * e + 1) % 40]);
                }
                kk0 = kk1;
            }
            const ull k32 = kc[32];
            #pragma unroll
            for (int j = 0; j < 8; ++j)
                acc[(i + j + 32) % 40] = ffma2(k32, bd[j], acc[(i + j + 32) % 40]);
            kc += 34;
        }
        // qy = s0+i .. s0+i+7 complete within this half: emit, recycle slots
        #pragma unroll
        for (int j = 0; j < 8; ++j) {
            const int qy = s0 + i + j;
            float2 v = *reinterpret_cast<float2*>(&acc[(i + j) % 40]);
            float* r = obase + (size_t)(irow0 + 2 * qy) * SENS + jcol;
            atomicAdd(r, v.x);
            if (emity) atomicAdd(r + 1, v.y);
            acc[(i + j) % 40] = 0ULL;
        }
    }

    // drain slots for local qy = 16..47
    #pragma unroll
    for (int d = 16; d < 48; ++d) {
        const int qy = s0 + d;
        if (ry == 1 && qy == 63) continue;          // oy = 127 out of block
        float2 v = *reinterpret_cast<float2*>(&acc[d % 40]);
        float* r = obase + (size_t)(irow0 + 2 * qy) * SENS + jcol;
        atomicAdd(r, v.x);
        if (emity) atomicAdd(r + 1, v.y);
    }
}

// ---------------- launch ----------------
extern "C" void kernel_launch(void* const* d_in, const int* in_sizes, int n_in,
                              void* d_out, int out_size) {
    const float* imgs = (const float*)d_in[0];
    const float* psf  = (const float*)d_in[1];
    const float* xc   = (const float*)d_in[4];
    const float* yc   = (const float*)d_in[5];
    float* out = (float*)d_out;

    (void)cudaFuncSetAttribute(conv_splat_kernel,
                               cudaFuncAttributeMaxDynamicSharedMemorySize, SMEM_BYTES);

    setup_kernel<<<ZERO_CTAS + BINPSF_CTAS, 256>>>(psf, (float4*)out);
    conv_splat_kernel<<<P_CNT * 2 * 8, 128, SMEM_BYTES>>>(imgs, xc, yc, out);
}